// round 1
// baseline (speedup 1.0000x reference)
#include <cuda_runtime.h>
#include <math.h>

// Per-row precomputed scalars (scratch; N=1536 in this problem, cap generous)
#define MAXN 4096
__device__ float g_x2[MAXN];   // ||x_i||^2
__device__ float g_l[MAXN];    // x_tan_i . w_l
__device__ float g_r[MAXN];    // x_tan_i . w_r

__device__ __forceinline__ float warp_sum(float v) {
#pragma unroll
    for (int o = 16; o; o >>= 1) v += __shfl_xor_sync(0xffffffffu, v, o);
    return v;  // result valid on all lanes (butterfly)
}

// One warp per row: norms + attention projections.
__global__ void pre_kernel(const float* __restrict__ x,
                           const float* __restrict__ att_w, int N) {
    int row  = blockIdx.x * (blockDim.x >> 5) + (threadIdx.x >> 5);
    int lane = threadIdx.x & 31;
    if (row >= N) return;
    float x0 = x[row * 64 + lane];
    float x1 = x[row * 64 + 32 + lane];
    float wl0 = att_w[lane],      wl1 = att_w[32 + lane];
    float wr0 = att_w[64 + lane], wr1 = att_w[96 + lane];
    float n2 = warp_sum(x0 * x0 + x1 * x1);
    float dl = warp_sum(x0 * wl0 + x1 * wl1);
    float dr = warp_sum(x0 * wr0 + x1 * wr1);
    float pn  = sqrtf(n2);
    float pnc = fmaxf(pn, 1e-15f);
    float s   = atanhf(fminf(pnc, 1.f - 1e-7f)) / pnc;  // logmap0 scale
    if (lane == 0) {
        g_x2[row] = n2;
        g_l[row]  = s * dl;
        g_r[row]  = s * dr;
    }
}

// One warp per row i: sparse scan of adj row, scalar-factored hyperbolic
// aggregation, fused expmap + proj epilogue.
__global__ void agg_kernel(const float* __restrict__ x,
                           const float* __restrict__ adj,
                           const float* __restrict__ att_b,
                           float* __restrict__ out, int N) {
    int row  = blockIdx.x * (blockDim.x >> 5) + (threadIdx.x >> 5);
    int lane = threadIdx.x & 31;
    if (row >= N) return;

    float bias = att_b[0];
    float xi0 = x[row * 64 + lane];
    float xi1 = x[row * 64 + 32 + lane];
    float x2   = g_x2[row];
    float li   = g_l[row];
    float beta = 1.f - x2;            // 1 - C*x2, C=1

    float acc0 = 0.f, acc1 = 0.f, S1 = 0.f;
    const float* arow = adj + (size_t)row * N;

    for (int j0 = 0; j0 < N; j0 += 128) {
        float a[4], rj[4], y2j[4];
#pragma unroll
        for (int c = 0; c < 4; c++) {   // 12 independent loads -> high MLP
            int j = j0 + c * 32 + lane;
            bool ok = (j < N);
            a[c]   = ok ? arow[j]  : 0.f;
            rj[c]  = ok ? g_r[j]   : 0.f;
            y2j[c] = ok ? g_x2[j]  : 0.f;
        }
#pragma unroll
        for (int c = 0; c < 4; c++) {
            unsigned m = __ballot_sync(0xffffffffu, a[c] != 0.f);
            while (m) {
                int b = __ffs(m) - 1; m &= m - 1;
                int jj = j0 + c * 32 + b;
                float xj0 = x[jj * 64 + lane];
                float xj1 = x[jj * 64 + 32 + lane];
                float Dd  = warp_sum(xi0 * xj0 + xi1 * xj1);   // <x_i, x_j>
                float y2  = __shfl_sync(0xffffffffu, y2j[c], b);
                float rv  = __shfl_sync(0xffffffffu, rj[c],  b);
                float av  = __shfl_sync(0xffffffffu, a[c],   b);
                // mobius_add(-x_i, x_j) scalar pieces (C=1, xy = -Dd)
                float alpha = 1.f - 2.f * Dd + y2;             // 1+2Cxy+Cy2
                float den   = fmaxf(1.f - 2.f * Dd + x2 * y2, 1e-15f);
                float n2    = alpha * alpha * x2 - 2.f * alpha * beta * Dd
                            + beta * beta * y2;                // ||num||^2
                float sn    = sqrtf(fmaxf(n2, 0.f)) / den;     // ||sub||
                sn = fmaxf(sn, 1e-15f);
                float ratio = atanhf(fminf(sn, 1.f - 1e-7f)) / sn;
                float z = li + rv + bias;
                float w = av / (1.f + expf(-z));               // sigmoid * adj
                float g = w * beta * ratio / den;
                acc0 = fmaf(g, xj0, acc0);
                acc1 = fmaf(g, xj1, acc1);
                S1   = fmaf(g, alpha, S1);
            }
        }
    }

    // support_t = beta * (sum g*x_j) - (sum g*alpha) * x_i
    float u0 = fmaf(beta, acc0, -S1 * xi0);
    float u1 = fmaf(beta, acc1, -S1 * xi1);

    // expmap(x_i, u)
    float un2 = warp_sum(u0 * u0 + u1 * u1);
    float du  = warp_sum(xi0 * u0 + xi1 * u1);
    float un  = fmaxf(sqrtf(un2), 1e-15f);
    float lam = fmaxf(2.f / beta, 1e-15f);
    float t   = tanhf(0.5f * lam * un);
    float sc  = t / un;                 // second = sc * u
    float s0 = sc * u0, s1 = sc * u1;
    float y2s = sc * sc * un2;          // ||second||^2
    float xys = sc * du;                // <x_i, second>
    float ca   = 1.f + 2.f * xys + y2s;
    float den2 = fmaxf(1.f + 2.f * xys + x2 * y2s, 1e-15f);
    float o0 = (ca * xi0 + beta * s0) / den2;
    float o1 = (ca * xi1 + beta * s1) / den2;

    // proj
    float on = fmaxf(sqrtf(warp_sum(o0 * o0 + o1 * o1)), 1e-15f);
    float maxn = 1.f - 0.004f;
    float scale = (on > maxn) ? (maxn / on) : 1.f;
    out[row * 64 + lane]      = o0 * scale;
    out[row * 64 + 32 + lane] = o1 * scale;
}

extern "C" void kernel_launch(void* const* d_in, const int* in_sizes, int n_in,
                              void* d_out, int out_size) {
    const float* x     = (const float*)d_in[0];
    const float* adj   = (const float*)d_in[1];
    const float* att_w = (const float*)d_in[2];
    const float* att_b = (const float*)d_in[3];
    int d = in_sizes[2] / 2;          // 64
    int N = in_sizes[0] / d;          // 1536
    const int WPB = 8;                // warps per block
    dim3 blk(32 * WPB);
    int grid = (N + WPB - 1) / WPB;
    pre_kernel<<<grid, blk>>>(x, att_w, N);
    agg_kernel<<<grid, blk>>>(x, adj, att_b, (float*)d_out, N);
}